// round 12
// baseline (speedup 1.0000x reference)
#include <cuda_runtime.h>
#include <cuda_bf16.h>
#include <stdint.h>

#define NN 20000
#define EE 320000
#define DD 512
#define BN_EPS 1e-5f

__device__ float4 g_Xbn[NN * 128];       // x_bn  [N, 512] fp32 (gather source)
__device__ float  g_invdeg[NN];
__device__ int    g_degi[NN];
__device__ int    g_cursor[NN];
__device__ int    g_rowptr[NN + 1];
__device__ int    g_csrc[EE];
__device__ __nv_bfloat16 g_Ah[(size_t)NN * 1024];   // A hi bf16 [N][1024]
__device__ __nv_bfloat16 g_Al[(size_t)NN * 1024];   // A lo bf16
__device__ __nv_bfloat16 g_Wh[4 * 512 * 1024];      // W hi bf16 [l][n][k]
__device__ __nv_bfloat16 g_Wl[4 * 512 * 1024];      // W lo bf16

__device__ __forceinline__ float4 f4add(float4 a, float4 b) {
    return make_float4(a.x + b.x, a.y + b.y, a.z + b.z, a.w + b.w);
}
__device__ __forceinline__ unsigned pack_hl(float a, float b, unsigned& lo) {
    __nv_bfloat162 h = __floats2bfloat162_rn(a, b);
    float2 hf = __bfloat1622float2(h);
    __nv_bfloat162 l = __floats2bfloat162_rn(a - hf.x, b - hf.y);
    lo = *reinterpret_cast<unsigned*>(&l);
    return *reinterpret_cast<unsigned*>(&h);
}

// ---------------------------------------------------------------------------
// CSR build
// ---------------------------------------------------------------------------
__global__ void k_zero() {
    int i = blockIdx.x * blockDim.x + threadIdx.x;
    if (i < NN) { g_degi[i] = 0; g_cursor[i] = 0; }
}
__global__ void k_count(const int* __restrict__ dst) {
    int e = blockIdx.x * blockDim.x + threadIdx.x;
    if (e < EE) atomicAdd(&g_degi[dst[e]], 1);
}
__global__ void k_invdeg() {
    int i = blockIdx.x * blockDim.x + threadIdx.x;
    if (i < NN) g_invdeg[i] = 1.f / fmaxf((float)g_degi[i], 1.f);
}
__global__ void k_scan() {
    __shared__ int ssum[1024];
    const int tid = threadIdx.x;
    const int per = (NN + 1023) / 1024;
    const int base = tid * per;
    int s = 0;
#pragma unroll 4
    for (int j = 0; j < per; j++) {
        int idx = base + j;
        if (idx < NN) s += g_degi[idx];
    }
    ssum[tid] = s;
    __syncthreads();
    for (int off = 1; off < 1024; off <<= 1) {
        int v = 0;
        if (tid >= off) v = ssum[tid - off];
        __syncthreads();
        ssum[tid] += v;
        __syncthreads();
    }
    int run = ssum[tid] - s;
#pragma unroll 4
    for (int j = 0; j < per; j++) {
        int idx = base + j;
        if (idx < NN) { g_rowptr[idx] = run; run += g_degi[idx]; }
    }
    if (tid == 1023) g_rowptr[NN] = EE;
}
__global__ void k_fill(const int* __restrict__ src, const int* __restrict__ dst) {
    int e = blockIdx.x * blockDim.x + threadIdx.x;
    if (e < EE) {
        int d = dst[e];
        int idx = atomicAdd(&g_cursor[d], 1);
        g_csrc[g_rowptr[d] + idx] = src[e];
    }
}

// ---------------------------------------------------------------------------
// Embedding fused with BN layer 0 -> Xbn fp32 + bf16 hi/lo A cols 512-1023
// ---------------------------------------------------------------------------
__global__ void k_embed_bn(const int* __restrict__ tok, const int* __restrict__ pos,
                           const float4* __restrict__ ve, const float4* __restrict__ pe,
                           const float4* __restrict__ ga, const float4* __restrict__ be,
                           const float4* __restrict__ me, const float4* __restrict__ va) {
    unsigned t = blockIdx.x * blockDim.x + threadIdx.x;
    unsigned i = t >> 7, c = t & 127u;
    if (i >= NN) return;
    float4 x = f4add(ve[(unsigned)tok[i] * 128 + c], pe[(unsigned)pos[i] * 128 + c]);
    float4 g = ga[c], b = be[c], m = me[c], v = va[c];
    float4 y;
    y.x = (x.x - m.x) * (g.x * rsqrtf(v.x + BN_EPS)) + b.x;
    y.y = (x.y - m.y) * (g.y * rsqrtf(v.y + BN_EPS)) + b.y;
    y.z = (x.z - m.z) * (g.z * rsqrtf(v.z + BN_EPS)) + b.z;
    y.w = (x.w - m.w) * (g.w * rsqrtf(v.w + BN_EPS)) + b.w;
    g_Xbn[i * 128 + c] = y;
    unsigned l0, l1;
    unsigned h0 = pack_hl(y.x, y.y, l0);
    unsigned h1 = pack_hl(y.z, y.w, l1);
    size_t o = (size_t)i * 1024 + 512 + c * 4;
    *(uint2*)&g_Ah[o] = make_uint2(h0, h1);
    *(uint2*)&g_Al[o] = make_uint2(l0, l1);
}

// ---------------------------------------------------------------------------
// CSR gather: agg[i] = invdeg * sum Xbn[csrc[e]] -> bf16 hi/lo A cols 0-511
// ---------------------------------------------------------------------------
__global__ __launch_bounds__(256) void k_gather() {
    const unsigned i = blockIdx.x * 2 + (threadIdx.x >> 7);
    const unsigned c = threadIdx.x & 127u;
    if (i >= NN) return;
    const int r0 = g_rowptr[i], r1 = g_rowptr[i + 1];
    float4 a0 = make_float4(0.f, 0.f, 0.f, 0.f);
    float4 a1 = a0;
    int e = r0;
    for (; e + 1 < r1; e += 2) {
        int s0 = __ldg(&g_csrc[e]);
        int s1 = __ldg(&g_csrc[e + 1]);
        a0 = f4add(a0, __ldg(&g_Xbn[(size_t)s0 * 128 + c]));
        a1 = f4add(a1, __ldg(&g_Xbn[(size_t)s1 * 128 + c]));
    }
    if (e < r1) {
        int s0 = __ldg(&g_csrc[e]);
        a0 = f4add(a0, __ldg(&g_Xbn[(size_t)s0 * 128 + c]));
    }
    a0 = f4add(a0, a1);
    const float sc = g_invdeg[i];
    a0.x *= sc; a0.y *= sc; a0.z *= sc; a0.w *= sc;
    unsigned l0, l1;
    unsigned h0 = pack_hl(a0.x, a0.y, l0);
    unsigned h1 = pack_hl(a0.z, a0.w, l1);
    size_t o = (size_t)i * 1024 + c * 4;
    *(uint2*)&g_Ah[o] = make_uint2(h0, h1);
    *(uint2*)&g_Al[o] = make_uint2(l0, l1);
}

// One-time: split W = [Wrel | Wroot] into bf16 hi/lo planes [l][n][1024].
__global__ void k_wconv(const float* __restrict__ Wrel, const float* __restrict__ Wroot) {
    unsigned t = blockIdx.x * blockDim.x + threadIdx.x;
    if (t >= 4u * 512u * 1024u / 4u) return;
    unsigned base = t * 4u;
    unsigned l = base >> 19;
    unsigned rem = base & 0x7FFFFu;
    unsigned n = rem >> 10;
    unsigned k = rem & 1023u;
    const float* srcp = (k < 512u)
        ? (Wrel + ((size_t)l * 512 + n) * 512 + k)
        : (Wroot + ((size_t)l * 512 + n) * 512 + (k - 512u));
    float4 v = *(const float4*)srcp;
    unsigned l0, l1;
    unsigned h0 = pack_hl(v.x, v.y, l0);
    unsigned h1 = pack_hl(v.z, v.w, l1);
    *(uint2*)&g_Wh[base] = make_uint2(h0, h1);
    *(uint2*)&g_Wl[base] = make_uint2(l0, l1);
}

// ===========================================================================
// mma.sync bf16 GEMM, 3-term split, CTA 128x256, Kc=32, 512 threads,
// 16 warps (2m x 8n), warp tile 64x32. 3-stage cp.async, ROWB=80.
// Epilogue fuses bias+relu and (layers 0-2) next layer's BN -> Xbn + A bf16.
// ===========================================================================
#define ROWB 80
#define S_AH 0
#define S_AL 10240
#define S_BH 20480
#define S_BL 40960
#define STAGE 61440
#define SMEM_DYN 184320

__device__ __forceinline__ uint32_t smem_u32(const void* p) {
    uint32_t a;
    asm("{ .reg .u64 t; cvta.to.shared.u64 t, %1; cvt.u32.u64 %0, t; }"
        : "=r"(a) : "l"(p));
    return a;
}
__device__ __forceinline__ void cpa16(uint32_t dst, const void* src, int sbytes) {
    asm volatile("cp.async.ca.shared.global [%0], [%1], 16, %2;"
                 :: "r"(dst), "l"(src), "r"(sbytes) : "memory");
}
__device__ __forceinline__ void ldm_x4(uint32_t* r, uint32_t addr) {
    asm volatile("ldmatrix.sync.aligned.m8n8.x4.shared.b16 {%0,%1,%2,%3}, [%4];"
                 : "=r"(r[0]), "=r"(r[1]), "=r"(r[2]), "=r"(r[3]) : "r"(addr));
}
__device__ __forceinline__ void mma16816(float* c, const uint32_t* a,
                                         uint32_t b0, uint32_t b1) {
    asm volatile(
        "mma.sync.aligned.m16n8k16.row.col.f32.bf16.bf16.f32 "
        "{%0,%1,%2,%3}, {%4,%5,%6,%7}, {%8,%9}, {%0,%1,%2,%3};"
        : "+f"(c[0]), "+f"(c[1]), "+f"(c[2]), "+f"(c[3])
        : "r"(a[0]), "r"(a[1]), "r"(a[2]), "r"(a[3]), "r"(b0), "r"(b1));
}

__global__ __launch_bounds__(512, 1) void k_gemm_mma(
    int lidx, const float* __restrict__ bias,
    const float* __restrict__ bn_g, const float* __restrict__ bn_b,
    const float* __restrict__ bn_m, const float* __restrict__ bn_v,
    float* __restrict__ outp, int applyBN) {
    extern __shared__ char sm[];
    const uint32_t smb = smem_u32(sm);

    const int tid = threadIdx.x;
    const int w = tid >> 5, lane = tid & 31;
    const int row0 = blockIdx.y * 128;
    const int nb0 = blockIdx.x * 256;

    // ---- cp.async mappings ----
    // A: 128 rows x 64B x 2 planes per chunk; thread -> row tid>>2, slot (tid&3)*16
    const int ar_ld = tid >> 2;
    const int as_ld = (tid & 3) * 16;
    const int agr = row0 + ar_ld;
    const int abytes = (agr < NN) ? 16 : 0;
    const char* pAh = (const char*)(g_Ah + (size_t)agr * 1024) + as_ld;
    const char* pAl = (const char*)(g_Al + (size_t)agr * 1024) + as_ld;
    const uint32_t adst = smb + ar_ld * ROWB + as_ld;
    // B: 256 rows x 64B x 2 planes; thread -> row tid>>1, 32B half (tid&1)*32
    const int br_ld = tid >> 1;
    const int bs_ld = (tid & 1) * 32;
    const char* pWh = (const char*)(g_Wh + ((size_t)lidx * 512 + nb0 + br_ld) * 1024) + bs_ld;
    const char* pWl = (const char*)(g_Wl + ((size_t)lidx * 512 + nb0 + br_ld) * 1024) + bs_ld;
    const uint32_t bdst = smb + br_ld * ROWB + bs_ld;

#define ISSUE(C)                                                              \
    {                                                                         \
        const int c_ = (C);                                                   \
        const uint32_t sb_ = ((c_) % 3) * STAGE;                              \
        const int go_ = c_ * 64;                                              \
        cpa16(adst + sb_ + S_AH, pAh + go_, abytes);                          \
        cpa16(adst + sb_ + S_AL, pAl + go_, abytes);                          \
        cpa16(bdst + sb_ + S_BH,      pWh + go_,      16);                    \
        cpa16(bdst + sb_ + S_BH + 16, pWh + go_ + 16, 16);                    \
        cpa16(bdst + sb_ + S_BL,      pWl + go_,      16);                    \
        cpa16(bdst + sb_ + S_BL + 16, pWl + go_ + 16, 16);                    \
        asm volatile("cp.async.commit_group;" ::: "memory");                  \
    }

    // ---- compute mapping: warp grid 2m x 8n, warp tile 64x32 ----
    const int wm0 = (w >> 3) * 64;
    const int wn0 = (w & 7) * 32;
    const int l8 = lane & 7, lq = lane >> 3;

    float acc[4][4][4];
#pragma unroll
    for (int i = 0; i < 4; i++)
#pragma unroll
        for (int j = 0; j < 4; j++)
#pragma unroll
            for (int k = 0; k < 4; k++) acc[i][j][k] = 0.f;

    ISSUE(0);
    ISSUE(1);

#pragma unroll 1
    for (int c = 0; c < 32; ++c) {
        if (c < 30) {
            asm volatile("cp.async.wait_group 1;" ::: "memory");
        } else {
            asm volatile("cp.async.wait_group 0;" ::: "memory");
        }
        __syncthreads();
        if (c < 30) ISSUE(c + 2);

        const uint32_t sb = smb + (c % 3) * STAGE;
#pragma unroll
        for (int ks = 0; ks < 2; ++ks) {
            const int kb = ks * 32;
            uint32_t ah[4][4], al[4][4], bh[2][4], bl[2][4];
            const int ar = wm0 + (lq & 1) * 8 + l8;
            const uint32_t akb = kb + (lq >> 1) * 16;
#pragma unroll
            for (int mi = 0; mi < 4; mi++) {
                uint32_t addr = sb + (ar + mi * 16) * ROWB + akb;
                ldm_x4(ah[mi], addr + S_AH);
                ldm_x4(al[mi], addr + S_AL);
            }
            const int br = wn0 + (lq >> 1) * 8 + l8;
            const uint32_t bkb = kb + (lq & 1) * 16;
#pragma unroll
            for (int ng = 0; ng < 2; ng++) {
                uint32_t addr = sb + (br + ng * 16) * ROWB + bkb;
                ldm_x4(bh[ng], addr + S_BH);
                ldm_x4(bl[ng], addr + S_BL);
            }
#pragma unroll
            for (int mi = 0; mi < 4; mi++)
#pragma unroll
                for (int ni = 0; ni < 4; ni++) {
                    const int g = ni >> 1, o = (ni & 1) * 2;
                    mma16816(acc[mi][ni], ah[mi], bh[g][o], bh[g][o + 1]);
                    mma16816(acc[mi][ni], ah[mi], bl[g][o], bl[g][o + 1]);
                    mma16816(acc[mi][ni], al[mi], bh[g][o], bh[g][o + 1]);
                }
        }
    }
#undef ISSUE

    // ---- epilogue: bias+relu (+ fused next-layer BN) ----
    const int lg = lane >> 2, lt = lane & 3;
#pragma unroll
    for (int ni = 0; ni < 4; ni++) {
        const int col = nb0 + wn0 + ni * 8 + lt * 2;
        const float b0 = __ldg(&bias[col]);
        const float b1 = __ldg(&bias[col + 1]);
        float i0 = 0.f, i1 = 0.f, m0 = 0.f, m1 = 0.f, bb0 = 0.f, bb1 = 0.f;
        if (applyBN) {
            i0 = __ldg(&bn_g[col]) * rsqrtf(__ldg(&bn_v[col]) + BN_EPS);
            i1 = __ldg(&bn_g[col + 1]) * rsqrtf(__ldg(&bn_v[col + 1]) + BN_EPS);
            m0 = __ldg(&bn_m[col]); m1 = __ldg(&bn_m[col + 1]);
            bb0 = __ldg(&bn_b[col]); bb1 = __ldg(&bn_b[col + 1]);
        }
#pragma unroll
        for (int mi = 0; mi < 4; mi++) {
#pragma unroll
            for (int half = 0; half < 2; half++) {
                const int r = row0 + wm0 + mi * 16 + half * 8 + lg;
                if (r >= NN) continue;
                float t0 = fmaxf(acc[mi][ni][half * 2 + 0] + b0, 0.f);
                float t1 = fmaxf(acc[mi][ni][half * 2 + 1] + b1, 0.f);
                if (applyBN) {
                    float y0 = (t0 - m0) * i0 + bb0;
                    float y1 = (t1 - m1) * i1 + bb1;
                    *(float2*)&((float*)g_Xbn)[(size_t)r * 512 + col] =
                        make_float2(y0, y1);
                    unsigned lo;
                    unsigned hi = pack_hl(y0, y1, lo);
                    size_t o = (size_t)r * 1024 + 512 + col;
                    *(unsigned*)&g_Ah[o] = hi;
                    *(unsigned*)&g_Al[o] = lo;
                } else {
                    *(float2*)&outp[(size_t)r * 512 + col] = make_float2(t0, t1);
                }
            }
        }
    }
}

// ---------------------------------------------------------------------------
extern "C" void kernel_launch(void* const* d_in, const int* in_sizes, int n_in,
                              void* d_out, int out_size) {
    (void)in_sizes; (void)n_in; (void)out_size;
    const int*   tokens = (const int*)d_in[0];
    const int*   pos    = (const int*)d_in[1];
    const int*   ei     = (const int*)d_in[2];
    const int*   src    = ei;
    const int*   dst    = ei + EE;
    const float* ve     = (const float*)d_in[3];
    const float* pe     = (const float*)d_in[4];
    const float* gamma  = (const float*)d_in[5];
    const float* beta   = (const float*)d_in[6];
    const float* mean   = (const float*)d_in[7];
    const float* var    = (const float*)d_in[8];
    const float* Wrel   = (const float*)d_in[9];
    const float* brel   = (const float*)d_in[10];
    const float* Wroot  = (const float*)d_in[11];
    float*       out    = (float*)d_out;

    cudaFuncSetAttribute(k_gemm_mma, cudaFuncAttributeMaxDynamicSharedMemorySize,
                         SMEM_DYN);

    // CSR build
    k_zero<<<(NN + 255) / 256, 256>>>();
    k_count<<<(EE + 255) / 256, 256>>>(dst);
    k_invdeg<<<(NN + 255) / 256, 256>>>();
    k_scan<<<1, 1024>>>();
    k_fill<<<(EE + 255) / 256, 256>>>(src, dst);

    k_embed_bn<<<(NN * 128) / 256, 256>>>(
        tokens, pos, (const float4*)ve, (const float4*)pe,
        (const float4*)gamma, (const float4*)beta,
        (const float4*)mean, (const float4*)var);
    k_wconv<<<(4 * 512 * 1024 / 4 + 255) / 256, 256>>>(Wrel, Wroot);

    for (int l = 0; l < 4; l++) {
        k_gather<<<(NN + 1) / 2, 256>>>();
        const int nl = (l < 3) ? (l + 1) : 0;   // BN params of next layer (unused for l=3)
        k_gemm_mma<<<dim3(2, 157), 512, SMEM_DYN>>>(
            l, brel + l * DD,
            gamma + nl * DD, beta + nl * DD, mean + nl * DD, var + nl * DD,
            out, (l < 3) ? 1 : 0);
    }
}

// round 15
// speedup vs baseline: 1.1422x; 1.1422x over previous
#include <cuda_runtime.h>
#include <cuda_bf16.h>
#include <stdint.h>

#define NN 20000
#define EE 320000
#define DD 512
#define BN_EPS 1e-5f

__device__ float4 g_Xbn[NN * 128];       // x_bn  [N, 512] fp32 (gather source)
__device__ float  g_invdeg[NN];
__device__ int    g_degi[NN];
__device__ int    g_cursor[NN];
__device__ int    g_rowptr[NN + 1];
__device__ int    g_csrc[EE];
__device__ __nv_bfloat16 g_Ah[(size_t)NN * 1024];   // A hi bf16 [N][1024]
__device__ __nv_bfloat16 g_Al[(size_t)NN * 1024];   // A lo bf16
__device__ __nv_bfloat16 g_Wh[4 * 512 * 1024];      // W hi bf16 [l][n][k]
__device__ __nv_bfloat16 g_Wl[4 * 512 * 1024];      // W lo bf16

__device__ __forceinline__ float4 f4add(float4 a, float4 b) {
    return make_float4(a.x + b.x, a.y + b.y, a.z + b.z, a.w + b.w);
}
__device__ __forceinline__ unsigned pack_hl(float a, float b, unsigned& lo) {
    __nv_bfloat162 h = __floats2bfloat162_rn(a, b);
    float2 hf = __bfloat1622float2(h);
    __nv_bfloat162 l = __floats2bfloat162_rn(a - hf.x, b - hf.y);
    lo = *reinterpret_cast<unsigned*>(&l);
    return *reinterpret_cast<unsigned*>(&h);
}

// ---------------------------------------------------------------------------
// CSR build
// ---------------------------------------------------------------------------
__global__ void k_zero() {
    int i = blockIdx.x * blockDim.x + threadIdx.x;
    if (i < NN) { g_degi[i] = 0; g_cursor[i] = 0; }
}
__global__ void k_count(const int* __restrict__ dst) {
    int e = blockIdx.x * blockDim.x + threadIdx.x;
    if (e < EE) atomicAdd(&g_degi[dst[e]], 1);
}
__global__ void k_invdeg() {
    int i = blockIdx.x * blockDim.x + threadIdx.x;
    if (i < NN) g_invdeg[i] = 1.f / fmaxf((float)g_degi[i], 1.f);
}
__global__ void k_scan() {
    __shared__ int ssum[1024];
    const int tid = threadIdx.x;
    const int per = (NN + 1023) / 1024;
    const int base = tid * per;
    int s = 0;
#pragma unroll 4
    for (int j = 0; j < per; j++) {
        int idx = base + j;
        if (idx < NN) s += g_degi[idx];
    }
    ssum[tid] = s;
    __syncthreads();
    for (int off = 1; off < 1024; off <<= 1) {
        int v = 0;
        if (tid >= off) v = ssum[tid - off];
        __syncthreads();
        ssum[tid] += v;
        __syncthreads();
    }
    int run = ssum[tid] - s;
#pragma unroll 4
    for (int j = 0; j < per; j++) {
        int idx = base + j;
        if (idx < NN) { g_rowptr[idx] = run; run += g_degi[idx]; }
    }
    if (tid == 1023) g_rowptr[NN] = EE;
}
__global__ void k_fill(const int* __restrict__ src, const int* __restrict__ dst) {
    int e = blockIdx.x * blockDim.x + threadIdx.x;
    if (e < EE) {
        int d = dst[e];
        int idx = atomicAdd(&g_cursor[d], 1);
        g_csrc[g_rowptr[d] + idx] = src[e];
    }
}

// ---------------------------------------------------------------------------
// Embedding fused with BN layer 0 -> Xbn fp32 + bf16 hi/lo A cols 512-1023
// ---------------------------------------------------------------------------
__global__ void k_embed_bn(const int* __restrict__ tok, const int* __restrict__ pos,
                           const float4* __restrict__ ve, const float4* __restrict__ pe,
                           const float4* __restrict__ ga, const float4* __restrict__ be,
                           const float4* __restrict__ me, const float4* __restrict__ va) {
    unsigned t = blockIdx.x * blockDim.x + threadIdx.x;
    unsigned i = t >> 7, c = t & 127u;
    if (i >= NN) return;
    float4 x = f4add(ve[(unsigned)tok[i] * 128 + c], pe[(unsigned)pos[i] * 128 + c]);
    float4 g = ga[c], b = be[c], m = me[c], v = va[c];
    float4 y;
    y.x = (x.x - m.x) * (g.x * rsqrtf(v.x + BN_EPS)) + b.x;
    y.y = (x.y - m.y) * (g.y * rsqrtf(v.y + BN_EPS)) + b.y;
    y.z = (x.z - m.z) * (g.z * rsqrtf(v.z + BN_EPS)) + b.z;
    y.w = (x.w - m.w) * (g.w * rsqrtf(v.w + BN_EPS)) + b.w;
    g_Xbn[i * 128 + c] = y;
    unsigned l0, l1;
    unsigned h0 = pack_hl(y.x, y.y, l0);
    unsigned h1 = pack_hl(y.z, y.w, l1);
    size_t o = (size_t)i * 1024 + 512 + c * 4;
    *(uint2*)&g_Ah[o] = make_uint2(h0, h1);
    *(uint2*)&g_Al[o] = make_uint2(l0, l1);
}

// ---------------------------------------------------------------------------
// CSR gather: agg[i] = invdeg * sum Xbn[csrc[e]] -> bf16 hi/lo A cols 0-511
// ---------------------------------------------------------------------------
__global__ __launch_bounds__(256) void k_gather() {
    const unsigned i = blockIdx.x * 2 + (threadIdx.x >> 7);
    const unsigned c = threadIdx.x & 127u;
    if (i >= NN) return;
    const int r0 = g_rowptr[i], r1 = g_rowptr[i + 1];
    float4 a0 = make_float4(0.f, 0.f, 0.f, 0.f);
    float4 a1 = a0;
    int e = r0;
    for (; e + 1 < r1; e += 2) {
        int s0 = __ldg(&g_csrc[e]);
        int s1 = __ldg(&g_csrc[e + 1]);
        a0 = f4add(a0, __ldg(&g_Xbn[(size_t)s0 * 128 + c]));
        a1 = f4add(a1, __ldg(&g_Xbn[(size_t)s1 * 128 + c]));
    }
    if (e < r1) {
        int s0 = __ldg(&g_csrc[e]);
        a0 = f4add(a0, __ldg(&g_Xbn[(size_t)s0 * 128 + c]));
    }
    a0 = f4add(a0, a1);
    const float sc = g_invdeg[i];
    a0.x *= sc; a0.y *= sc; a0.z *= sc; a0.w *= sc;
    unsigned l0, l1;
    unsigned h0 = pack_hl(a0.x, a0.y, l0);
    unsigned h1 = pack_hl(a0.z, a0.w, l1);
    size_t o = (size_t)i * 1024 + c * 4;
    *(uint2*)&g_Ah[o] = make_uint2(h0, h1);
    *(uint2*)&g_Al[o] = make_uint2(l0, l1);
}

// One-time: split W = [Wrel | Wroot] into bf16 hi/lo planes [l][n][1024].
__global__ void k_wconv(const float* __restrict__ Wrel, const float* __restrict__ Wroot) {
    unsigned t = blockIdx.x * blockDim.x + threadIdx.x;
    if (t >= 4u * 512u * 1024u / 4u) return;
    unsigned base = t * 4u;
    unsigned l = base >> 19;
    unsigned rem = base & 0x7FFFFu;
    unsigned n = rem >> 10;
    unsigned k = rem & 1023u;
    const float* srcp = (k < 512u)
        ? (Wrel + ((size_t)l * 512 + n) * 512 + k)
        : (Wroot + ((size_t)l * 512 + n) * 512 + (k - 512u));
    float4 v = *(const float4*)srcp;
    unsigned l0, l1;
    unsigned h0 = pack_hl(v.x, v.y, l0);
    unsigned h1 = pack_hl(v.z, v.w, l1);
    *(uint2*)&g_Wh[base] = make_uint2(h0, h1);
    *(uint2*)&g_Wl[base] = make_uint2(l0, l1);
}

// ===========================================================================
// mma.sync bf16 GEMM, 3-term split, CTA 128x128, Kc=32, 256 threads,
// 8 warps (2m x 4n), warp tile 64x32, 3-stage cp.async, ROWB=80.
// Epilogue: bias+relu, and for layers 0-2 fused next-layer BN -> Xbn + A bf16.
// ===========================================================================
#define ROWB 80
#define S_AH 0
#define S_AL 10240
#define S_BH 20480
#define S_BL 30720
#define STAGE 40960
#define SMEM_DYN 122880

__device__ __forceinline__ uint32_t smem_u32(const void* p) {
    uint32_t a;
    asm("{ .reg .u64 t; cvta.to.shared.u64 t, %1; cvt.u32.u64 %0, t; }"
        : "=r"(a) : "l"(p));
    return a;
}
__device__ __forceinline__ void cpa16(uint32_t dst, const void* src, int sbytes) {
    asm volatile("cp.async.ca.shared.global [%0], [%1], 16, %2;"
                 :: "r"(dst), "l"(src), "r"(sbytes) : "memory");
}
__device__ __forceinline__ void ldm_x4(uint32_t* r, uint32_t addr) {
    asm volatile("ldmatrix.sync.aligned.m8n8.x4.shared.b16 {%0,%1,%2,%3}, [%4];"
                 : "=r"(r[0]), "=r"(r[1]), "=r"(r[2]), "=r"(r[3]) : "r"(addr));
}
__device__ __forceinline__ void mma16816(float* c, const uint32_t* a,
                                         uint32_t b0, uint32_t b1) {
    asm volatile(
        "mma.sync.aligned.m16n8k16.row.col.f32.bf16.bf16.f32 "
        "{%0,%1,%2,%3}, {%4,%5,%6,%7}, {%8,%9}, {%0,%1,%2,%3};"
        : "+f"(c[0]), "+f"(c[1]), "+f"(c[2]), "+f"(c[3])
        : "r"(a[0]), "r"(a[1]), "r"(a[2]), "r"(a[3]), "r"(b0), "r"(b1));
}

__global__ __launch_bounds__(256, 1) void k_gemm_mma(
    int lidx, const float* __restrict__ bias,
    const float* __restrict__ bn_g, const float* __restrict__ bn_b,
    const float* __restrict__ bn_m, const float* __restrict__ bn_v,
    float* __restrict__ outp, int applyBN) {
    extern __shared__ char sm[];
    const uint32_t smb = smem_u32(sm);

    const int tid = threadIdx.x;
    const int w = tid >> 5, lane = tid & 31;
    const int row0 = blockIdx.y * 128;
    const int nb0 = blockIdx.x * 128;

    // ---- async-copy mapping: row = tid>>1, 32B half = (tid&1)*32 ----
    const int crow = tid >> 1;
    const int csp = (tid & 1) * 32;
    const int agr = row0 + crow;
    const int abytes = (agr < NN) ? 16 : 0;
    const char* pAh = (const char*)g_Ah + ((size_t)agr * 2048) + csp;
    const char* pAl = (const char*)g_Al + ((size_t)agr * 2048) + csp;
    const char* pWh = (const char*)(g_Wh + ((size_t)lidx * 512 + nb0 + crow) * 1024) + csp;
    const char* pWl = (const char*)(g_Wl + ((size_t)lidx * 512 + nb0 + crow) * 1024) + csp;
    const uint32_t sdst = smb + crow * ROWB + csp;

#define ISSUE(C)                                                              \
    {                                                                         \
        const int c_ = (C);                                                   \
        const uint32_t sb_ = ((c_) % 3) * STAGE;                              \
        const int go_ = c_ * 64;                                              \
        cpa16(sdst + sb_ + S_AH,      pAh + go_,      abytes);                \
        cpa16(sdst + sb_ + S_AH + 16, pAh + go_ + 16, abytes);                \
        cpa16(sdst + sb_ + S_AL,      pAl + go_,      abytes);                \
        cpa16(sdst + sb_ + S_AL + 16, pAl + go_ + 16, abytes);                \
        cpa16(sdst + sb_ + S_BH,      pWh + go_,      16);                    \
        cpa16(sdst + sb_ + S_BH + 16, pWh + go_ + 16, 16);                    \
        cpa16(sdst + sb_ + S_BL,      pWl + go_,      16);                    \
        cpa16(sdst + sb_ + S_BL + 16, pWl + go_ + 16, 16);                    \
        asm volatile("cp.async.commit_group;" ::: "memory");                  \
    }

    // ---- compute mapping: warp grid 2m x 4n, warp tile 64x32 ----
    const int wm0 = (w >> 2) * 64;
    const int wn0 = (w & 3) * 32;
    const int l8 = lane & 7, lq = lane >> 3;

    float acc[4][4][4];
#pragma unroll
    for (int i = 0; i < 4; i++)
#pragma unroll
        for (int j = 0; j < 4; j++)
#pragma unroll
            for (int k = 0; k < 4; k++) acc[i][j][k] = 0.f;

    ISSUE(0);
    ISSUE(1);

#pragma unroll 1
    for (int c = 0; c < 32; ++c) {
        if (c < 30) {
            asm volatile("cp.async.wait_group 1;" ::: "memory");
        } else {
            asm volatile("cp.async.wait_group 0;" ::: "memory");
        }
        __syncthreads();
        if (c < 30) ISSUE(c + 2);

        const uint32_t sb = smb + (c % 3) * STAGE;
#pragma unroll
        for (int ks = 0; ks < 2; ++ks) {
            const int kb = ks * 32;
            uint32_t ah[4][4], al[4][4], bh[2][4], bl[2][4];
            const int ar = wm0 + (lq & 1) * 8 + l8;
            const uint32_t akb = kb + (lq >> 1) * 16;
#pragma unroll
            for (int mi = 0; mi < 4; mi++) {
                uint32_t addr = sb + (ar + mi * 16) * ROWB + akb;
                ldm_x4(ah[mi], addr + S_AH);
                ldm_x4(al[mi], addr + S_AL);
            }
            const int br = wn0 + (lq >> 1) * 8 + l8;
            const uint32_t bkb = kb + (lq & 1) * 16;
#pragma unroll
            for (int ng = 0; ng < 2; ng++) {
                uint32_t addr = sb + (br + ng * 16) * ROWB + bkb;
                ldm_x4(bh[ng], addr + S_BH);
                ldm_x4(bl[ng], addr + S_BL);
            }
#pragma unroll
            for (int mi = 0; mi < 4; mi++)
#pragma unroll
                for (int ni = 0; ni < 4; ni++) {
                    const int g = ni >> 1, o = (ni & 1) * 2;
                    mma16816(acc[mi][ni], ah[mi], bh[g][o], bh[g][o + 1]);
                    mma16816(acc[mi][ni], ah[mi], bl[g][o], bl[g][o + 1]);
                    mma16816(acc[mi][ni], al[mi], bh[g][o], bh[g][o + 1]);
                }
        }
    }
#undef ISSUE

    // ---- epilogue: bias+relu (+ fused next-layer BN) ----
    const int lg = lane >> 2, lt = lane & 3;
#pragma unroll
    for (int ni = 0; ni < 4; ni++) {
        const int col = nb0 + wn0 + ni * 8 + lt * 2;
        const float b0 = __ldg(&bias[col]);
        const float b1 = __ldg(&bias[col + 1]);
        float i0 = 0.f, i1 = 0.f, m0 = 0.f, m1 = 0.f, bb0 = 0.f, bb1 = 0.f;
        if (applyBN) {
            i0 = __ldg(&bn_g[col]) * rsqrtf(__ldg(&bn_v[col]) + BN_EPS);
            i1 = __ldg(&bn_g[col + 1]) * rsqrtf(__ldg(&bn_v[col + 1]) + BN_EPS);
            m0 = __ldg(&bn_m[col]); m1 = __ldg(&bn_m[col + 1]);
            bb0 = __ldg(&bn_b[col]); bb1 = __ldg(&bn_b[col + 1]);
        }
#pragma unroll
        for (int mi = 0; mi < 4; mi++) {
#pragma unroll
            for (int half = 0; half < 2; half++) {
                const int r = row0 + wm0 + mi * 16 + half * 8 + lg;
                if (r >= NN) continue;
                float t0 = fmaxf(acc[mi][ni][half * 2 + 0] + b0, 0.f);
                float t1 = fmaxf(acc[mi][ni][half * 2 + 1] + b1, 0.f);
                if (applyBN) {
                    float y0 = (t0 - m0) * i0 + bb0;
                    float y1 = (t1 - m1) * i1 + bb1;
                    *(float2*)&((float*)g_Xbn)[(size_t)r * 512 + col] =
                        make_float2(y0, y1);
                    unsigned lo;
                    unsigned hi = pack_hl(y0, y1, lo);
                    size_t o = (size_t)r * 1024 + 512 + col;
                    *(unsigned*)&g_Ah[o] = hi;
                    *(unsigned*)&g_Al[o] = lo;
                } else {
                    *(float2*)&outp[(size_t)r * 512 + col] = make_float2(t0, t1);
                }
            }
        }
    }
}

// ---------------------------------------------------------------------------
extern "C" void kernel_launch(void* const* d_in, const int* in_sizes, int n_in,
                              void* d_out, int out_size) {
    (void)in_sizes; (void)n_in; (void)out_size;
    const int*   tokens = (const int*)d_in[0];
    const int*   pos    = (const int*)d_in[1];
    const int*   ei     = (const int*)d_in[2];
    const int*   src    = ei;
    const int*   dst    = ei + EE;
    const float* ve     = (const float*)d_in[3];
    const float* pe     = (const float*)d_in[4];
    const float* gamma  = (const float*)d_in[5];
    const float* beta   = (const float*)d_in[6];
    const float* mean   = (const float*)d_in[7];
    const float* var    = (const float*)d_in[8];
    const float* Wrel   = (const float*)d_in[9];
    const float* brel   = (const float*)d_in[10];
    const float* Wroot  = (const float*)d_in[11];
    float*       out    = (float*)d_out;

    cudaFuncSetAttribute(k_gemm_mma, cudaFuncAttributeMaxDynamicSharedMemorySize,
                         SMEM_DYN);

    // CSR build
    k_zero<<<(NN + 255) / 256, 256>>>();
    k_count<<<(EE + 255) / 256, 256>>>(dst);
    k_invdeg<<<(NN + 255) / 256, 256>>>();
    k_scan<<<1, 1024>>>();
    k_fill<<<(EE + 255) / 256, 256>>>(src, dst);

    k_embed_bn<<<(NN * 128) / 256, 256>>>(
        tokens, pos, (const float4*)ve, (const float4*)pe,
        (const float4*)gamma, (const float4*)beta,
        (const float4*)mean, (const float4*)var);
    k_wconv<<<(4 * 512 * 1024 / 4 + 255) / 256, 256>>>(Wrel, Wroot);

    for (int l = 0; l < 4; l++) {
        k_gather<<<(NN + 1) / 2, 256>>>();
        const int nl = (l < 3) ? (l + 1) : 0;
        k_gemm_mma<<<dim3(4, 157), 256, SMEM_DYN>>>(
            l, brel + l * DD,
            gamma + nl * DD, beta + nl * DD, mean + nl * DD, var + nl * DD,
            out, (l < 3) ? 1 : 0);
    }
}